// round 5
// baseline (speedup 1.0000x reference)
#include <cuda_runtime.h>
#include <math.h>
#include <stdint.h>

// Problem constants
#define BATCH 2
#define SEQ   2048
#define DIM   1024
#define NH    16
#define HD    64
#define DFF_N 4096
#define ATT   256
#define MROWS (BATCH * SEQ)   // 4096

// ---------------- scratch (device globals; no allocation allowed) ----------
__device__ float g_q  [MROWS * DIM];
__device__ float g_k  [MROWS * DIM];
__device__ float g_v  [MROWS * DIM];
__device__ float g_ctx[MROWS * DIM];
__device__ float g_sa [MROWS * DIM];
__device__ float g_x1 [MROWS * DIM];
__device__ float g_h  [MROWS * DFF_N];
__device__ float g_y  [MROWS * DIM];

// ---------------- helpers ---------------------------------------------------
__device__ __forceinline__ float gelu_exact(float v) {
    return 0.5f * v * (1.0f + erff(v * 0.7071067811865476f));
}
__device__ __forceinline__ uint32_t f2tf32(float v) {
    uint32_t r;
    asm("cvt.rna.tf32.f32 %0, %1;" : "=r"(r) : "f"(v));
    return r;
}
__device__ __forceinline__ void mma_tf32(float* c, const uint32_t* a, const uint32_t* b) {
    asm volatile(
        "mma.sync.aligned.m16n8k8.row.col.f32.tf32.tf32.f32 "
        "{%0,%1,%2,%3}, {%4,%5,%6,%7}, {%8,%9}, {%0,%1,%2,%3};"
        : "+f"(c[0]), "+f"(c[1]), "+f"(c[2]), "+f"(c[3])
        : "r"(a[0]), "r"(a[1]), "r"(a[2]), "r"(a[3]), "r"(b[0]), "r"(b[1]));
}

// =====================================================================
// mma.sync tf32 GEMM: C = A[M,K] @ B[K,N] (+bias)(+res)(+gelu)
// BM=BN=128, BK=16, 256 thr (8 warps 2x4), warp tile 64x32.
// Smem holds tf32 fragments in per-lane order: mainloop = LDS.128/LDS.64.
// EPI: 0 = +bias, 1 = +bias+res, 2 = gelu(+bias)
// =====================================================================
#define GBK 16

template <int EPI>
__global__ __launch_bounds__(256, 2)
void gemm_mma(const float* __restrict__ A,
              const float* __restrict__ B,
              const float* __restrict__ bias,
              const float* __restrict__ res,
              float* __restrict__ C,
              int M, int N, int Kd)
{
    // [buf][(kstep*8+mtile)*32+lane][4] / [buf][(kstep*16+ntile)*32+lane][2]
    __shared__ uint32_t Asm[2][2048];
    __shared__ uint32_t Bsm[2][2048];

    const int tid  = threadIdx.x;
    const int wid  = tid >> 5;
    const int lane = tid & 31;
    const int wm   = wid >> 2;   // 0..1 (M)
    const int wn   = wid & 3;    // 0..3 (N)
    const int bm   = blockIdx.y * 128;
    const int bn   = blockIdx.x * 128;

    float c[16][4];
    #pragma unroll
    for (int i = 0; i < 16; i++)
        #pragma unroll
        for (int j = 0; j < 4; j++) c[i][j] = 0.f;

    const int T = Kd / GBK;

    float4 av[2], bv[2];
    // thread's fixed tile coords
    // A: idx = tid + i*256 -> row=idx>>2 (0..127), c4=idx&3
    // B: idx = tid + i*256 -> krow=idx>>5 (0..15), c4=idx&31

    // ---- load chunk 0 ----
    #pragma unroll
    for (int i = 0; i < 2; i++) {
        int idx = tid + i * 256;
        av[i] = *(const float4*)&A[(size_t)(bm + (idx >> 2)) * Kd + (idx & 3) * 4];
        bv[i] = *(const float4*)&B[(size_t)(idx >> 5) * N + bn + (idx & 31) * 4];
    }
    // ---- scatter chunk 0 into buf 0 ----
    #pragma unroll
    for (int i = 0; i < 2; i++) {
        int idx = tid + i * 256;
        {
            int row = idx >> 2, c0 = (idx & 3) * 4;
            int mtile = row >> 4, r16 = row & 15;
            int g = r16 & 7, rhi = r16 >> 3;
            float vv[4] = {av[i].x, av[i].y, av[i].z, av[i].w};
            #pragma unroll
            for (int j = 0; j < 4; j++) {
                int cf = c0 + j, ks = cf >> 3, cc = cf & 7;
                int reg = rhi + ((cc >> 2) << 1);
                Asm[0][((ks * 8 + mtile) * 32 + g * 4 + (cc & 3)) * 4 + reg] = f2tf32(vv[j]);
            }
        }
        {
            int k = idx >> 5, c0 = (idx & 31) * 4;
            int ks = k >> 3, kk = k & 7;
            int reg = kk >> 2, t = kk & 3;
            float vv[4] = {bv[i].x, bv[i].y, bv[i].z, bv[i].w};
            #pragma unroll
            for (int j = 0; j < 4; j++) {
                int n = c0 + j;
                Bsm[0][((ks * 16 + (n >> 3)) * 32 + (n & 7) * 4 + t) * 2 + reg] = f2tf32(vv[j]);
            }
        }
    }
    __syncthreads();

    // ---- main loop ----
    for (int t = 0; t < T; t++) {
        const int p = t & 1;
        if (t + 1 < T) {
            const int k0 = (t + 1) * GBK;
            #pragma unroll
            for (int i = 0; i < 2; i++) {
                int idx = tid + i * 256;
                av[i] = *(const float4*)&A[(size_t)(bm + (idx >> 2)) * Kd + k0 + (idx & 3) * 4];
                bv[i] = *(const float4*)&B[(size_t)(k0 + (idx >> 5)) * N + bn + (idx & 31) * 4];
            }
        }

        // compute on buffer p (2 k-steps of 8)
        #pragma unroll
        for (int ks = 0; ks < 2; ks++) {
            uint32_t a[4][4], b[4][2];
            #pragma unroll
            for (int i = 0; i < 4; i++) {
                const uint32_t* ptr = &Asm[p][((ks * 8 + wm * 4 + i) * 32 + lane) * 4];
                a[i][0] = ptr[0]; a[i][1] = ptr[1]; a[i][2] = ptr[2]; a[i][3] = ptr[3];
            }
            #pragma unroll
            for (int j = 0; j < 4; j++) {
                const uint32_t* ptr = &Bsm[p][((ks * 16 + wn * 4 + j) * 32 + lane) * 2];
                b[j][0] = ptr[0]; b[j][1] = ptr[1];
            }
            #pragma unroll
            for (int i = 0; i < 4; i++)
                #pragma unroll
                for (int j = 0; j < 4; j++)
                    mma_tf32(c[i * 4 + j], a[i], b[j]);
        }

        if (t + 1 < T) {
            const int np = p ^ 1;
            #pragma unroll
            for (int i = 0; i < 2; i++) {
                int idx = tid + i * 256;
                {
                    int row = idx >> 2, c0 = (idx & 3) * 4;
                    int mtile = row >> 4, r16 = row & 15;
                    int g = r16 & 7, rhi = r16 >> 3;
                    float vv[4] = {av[i].x, av[i].y, av[i].z, av[i].w};
                    #pragma unroll
                    for (int j = 0; j < 4; j++) {
                        int cf = c0 + j, ks = cf >> 3, cc = cf & 7;
                        int reg = rhi + ((cc >> 2) << 1);
                        Asm[np][((ks * 8 + mtile) * 32 + g * 4 + (cc & 3)) * 4 + reg] = f2tf32(vv[j]);
                    }
                }
                {
                    int k = idx >> 5, c0 = (idx & 31) * 4;
                    int ks = k >> 3, kk = k & 7;
                    int reg = kk >> 2, tt = kk & 3;
                    float vv[4] = {bv[i].x, bv[i].y, bv[i].z, bv[i].w};
                    #pragma unroll
                    for (int j = 0; j < 4; j++) {
                        int n = c0 + j;
                        Bsm[np][((ks * 16 + (n >> 3)) * 32 + (n & 7) * 4 + tt) * 2 + reg] = f2tf32(vv[j]);
                    }
                }
            }
            __syncthreads();
        }
    }

    // ---- epilogue ----
    const int g = lane >> 2, tq = lane & 3;
    #pragma unroll
    for (int i = 0; i < 4; i++) {
        const int r0 = bm + wm * 64 + i * 16 + g;
        #pragma unroll
        for (int j = 0; j < 4; j++) {
            const int cb = bn + wn * 32 + j * 8 + tq * 2;
            float2 bs = *(const float2*)&bias[cb];
            float o0 = c[i * 4 + j][0] + bs.x;
            float o1 = c[i * 4 + j][1] + bs.y;
            float o2 = c[i * 4 + j][2] + bs.x;
            float o3 = c[i * 4 + j][3] + bs.y;
            if (EPI == 1) {
                float2 r0v = *(const float2*)&res[(size_t)r0 * N + cb];
                float2 r1v = *(const float2*)&res[(size_t)(r0 + 8) * N + cb];
                o0 += r0v.x; o1 += r0v.y; o2 += r1v.x; o3 += r1v.y;
            }
            if (EPI == 2) {
                o0 = gelu_exact(o0); o1 = gelu_exact(o1);
                o2 = gelu_exact(o2); o3 = gelu_exact(o3);
            }
            float2 w0 = {o0, o1}, w1 = {o2, o3};
            *(float2*)&C[(size_t)r0 * N + cb]       = w0;
            *(float2*)&C[(size_t)(r0 + 8) * N + cb] = w1;
        }
    }
}

// =====================================================================
// Banded attention (R2): 64-query tiles, fp32 FFMA.
// =====================================================================
#define NEGBIG (-1e30f)

__global__ __launch_bounds__(256, 2)
void attn_kernel(const float* __restrict__ Q,
                 const float* __restrict__ Kmat,
                 const float* __restrict__ V,
                 float* __restrict__ O)
{
    __shared__ float Qt[64][64];
    __shared__ float Kt[64][64];
    __shared__ float Vs[64][64];

    const int tid = threadIdx.x;
    const int tx  = tid & 15;
    const int ty  = tid >> 4;
    const int q0  = blockIdx.x * 64;
    const int h   = blockIdx.y;
    const int b   = blockIdx.z;

    const float scale = 0.022097086912079608f; // 1/sqrt(2048)
    const size_t headbase = (size_t)b * SEQ * DIM + (size_t)h * HD;

    {
        const int lq = tid >> 4;
        const int d0 = (tid & 15) * 4;
        const int c  = ((d0 >> 2) & 7) << 2;
        #pragma unroll
        for (int r = 0; r < 4; r++) {
            int q = r * 16 + lq;
            float4 v4 = *(const float4*)&Q[headbase + (size_t)(q0 + q) * DIM + d0];
            Qt[d0 + 0][q ^ c] = v4.x;
            Qt[d0 + 1][q ^ c] = v4.y;
            Qt[d0 + 2][q ^ c] = v4.z;
            Qt[d0 + 3][q ^ c] = v4.w;
        }
    }

    const int jlo = max(q0 - ATT, 0);
    const int jhi = min(q0 + 63 + ATT, SEQ - 1);

    float acc[4][4];
    #pragma unroll
    for (int i = 0; i < 4; i++)
        #pragma unroll
        for (int j = 0; j < 4; j++) acc[i][j] = 0.f;
    float mrow[4] = {NEGBIG, NEGBIG, NEGBIG, NEGBIG};
    float lrow[4] = {0.f, 0.f, 0.f, 0.f};

    for (int j0 = jlo; j0 <= jhi; j0 += 64) {
        __syncthreads();
        {
            const int lk = tid >> 4;
            const int d0 = (tid & 15) * 4;
            const int c  = ((d0 >> 2) & 7) << 2;
            #pragma unroll
            for (int r = 0; r < 4; r++) {
                int k = r * 16 + lk;
                size_t off = headbase + (size_t)(j0 + k) * DIM + d0;
                float4 kv = *(const float4*)&Kmat[off];
                Kt[d0 + 0][k ^ c] = kv.x;
                Kt[d0 + 1][k ^ c] = kv.y;
                Kt[d0 + 2][k ^ c] = kv.z;
                Kt[d0 + 3][k ^ c] = kv.w;
                *(float4*)&Vs[k][d0] = *(const float4*)&V[off];
            }
        }
        __syncthreads();

        float s[4][4];
        #pragma unroll
        for (int i = 0; i < 4; i++)
            #pragma unroll
            for (int j = 0; j < 4; j++) s[i][j] = 0.f;
        #pragma unroll 8
        for (int kk = 0; kk < 64; kk++) {
            const int c = ((kk >> 2) & 7) << 2;
            float4 a4 = *(const float4*)&Qt[kk][(ty * 4) ^ c];
            float4 b4 = *(const float4*)&Kt[kk][(tx * 4) ^ c];
            float a[4] = {a4.x, a4.y, a4.z, a4.w};
            float bb[4] = {b4.x, b4.y, b4.z, b4.w};
            #pragma unroll
            for (int i = 0; i < 4; i++)
                #pragma unroll
                for (int j = 0; j < 4; j++)
                    s[i][j] = fmaf(a[i], bb[j], s[i][j]);
        }

        #pragma unroll
        for (int i = 0; i < 4; i++) {
            int q = q0 + ty * 4 + i;
            #pragma unroll
            for (int j = 0; j < 4; j++) {
                int k = j0 + tx * 4 + j;
                int d = q - k;
                if (d > ATT || d < -ATT) s[i][j] = NEGBIG;
                else                      s[i][j] *= scale;
            }
        }

        float alpha[4];
        #pragma unroll
        for (int i = 0; i < 4; i++) {
            float cm = fmaxf(fmaxf(s[i][0], s[i][1]), fmaxf(s[i][2], s[i][3]));
            cm = fmaxf(cm, __shfl_xor_sync(0xffffffffu, cm, 1));
            cm = fmaxf(cm, __shfl_xor_sync(0xffffffffu, cm, 2));
            cm = fmaxf(cm, __shfl_xor_sync(0xffffffffu, cm, 4));
            cm = fmaxf(cm, __shfl_xor_sync(0xffffffffu, cm, 8));
            float mn = fmaxf(mrow[i], cm);
            alpha[i] = __expf(mrow[i] - mn);
            float psum = 0.f;
            #pragma unroll
            for (int j = 0; j < 4; j++) {
                s[i][j] = __expf(s[i][j] - mn);
                psum += s[i][j];
            }
            psum += __shfl_xor_sync(0xffffffffu, psum, 1);
            psum += __shfl_xor_sync(0xffffffffu, psum, 2);
            psum += __shfl_xor_sync(0xffffffffu, psum, 4);
            psum += __shfl_xor_sync(0xffffffffu, psum, 8);
            lrow[i] = lrow[i] * alpha[i] + psum;
            mrow[i] = mn;
            #pragma unroll
            for (int j = 0; j < 4; j++) acc[i][j] *= alpha[i];
        }

        __syncthreads();

        #pragma unroll
        for (int j = 0; j < 4; j++) {
            int k = tx * 4 + j;
            int c = ((k >> 2) & 7) << 2;
            #pragma unroll
            for (int i = 0; i < 4; i++)
                Kt[k][(ty * 4 + i) ^ c] = s[i][j];
        }
        __syncthreads();

        #pragma unroll 8
        for (int kk = 0; kk < 64; kk++) {
            const int c = ((kk >> 2) & 7) << 2;
            float4 a4 = *(const float4*)&Kt[kk][(ty * 4) ^ c];
            float4 b4 = *(const float4*)&Vs[kk][tx * 4];
            float a[4] = {a4.x, a4.y, a4.z, a4.w};
            float bb[4] = {b4.x, b4.y, b4.z, b4.w};
            #pragma unroll
            for (int i = 0; i < 4; i++)
                #pragma unroll
                for (int j = 0; j < 4; j++)
                    acc[i][j] = fmaf(a[i], bb[j], acc[i][j]);
        }
    }

    #pragma unroll
    for (int i = 0; i < 4; i++) {
        float inv = 1.0f / lrow[i];
        int q = q0 + ty * 4 + i;
        float4 ov = {acc[i][0] * inv, acc[i][1] * inv,
                     acc[i][2] * inv, acc[i][3] * inv};
        *(float4*)&O[headbase + (size_t)q * DIM + tx * 4] = ov;
    }
}

// ---------------- LayerNorm -------------------------------------------------
__global__ void ln_kernel(const float* __restrict__ X,
                          const float* __restrict__ g,
                          const float* __restrict__ bb,
                          float* __restrict__ Y)
{
    const int row = blockIdx.x;
    const int tid = threadIdx.x;
    const float* x = X + (size_t)row * DIM;
    __shared__ float red[256];

    float s = 0.f, s2 = 0.f;
    for (int c = tid; c < DIM; c += 256) {
        float v = x[c];
        s  += v;
        s2 += v * v;
    }

    red[tid] = s; __syncthreads();
    for (int o = 128; o > 0; o >>= 1) {
        if (tid < o) red[tid] += red[tid + o];
        __syncthreads();
    }
    const float mu = red[0] * (1.0f / DIM);
    __syncthreads();

    red[tid] = s2; __syncthreads();
    for (int o = 128; o > 0; o >>= 1) {
        if (tid < o) red[tid] += red[tid + o];
        __syncthreads();
    }
    const float var = red[0] * (1.0f / DIM) - mu * mu;
    const float inv = rsqrtf(var + 1e-5f);

    for (int c = tid; c < DIM; c += 256) {
        Y[(size_t)row * DIM + c] = (x[c] - mu) * inv * g[c] + bb[c];
    }
}

// ---------------- launch ----------------------------------------------------
extern "C" void kernel_launch(void* const* d_in, const int* in_sizes, int n_in,
                              void* d_out, int out_size)
{
    const float* x    = (const float*)d_in[0];
    const float* Wq   = (const float*)d_in[1];
    const float* bq   = (const float*)d_in[2];
    const float* Wk   = (const float*)d_in[3];
    const float* bk   = (const float*)d_in[4];
    const float* Wv   = (const float*)d_in[5];
    const float* bv   = (const float*)d_in[6];
    const float* Wo   = (const float*)d_in[7];
    const float* bo   = (const float*)d_in[8];
    const float* W1   = (const float*)d_in[9];
    const float* b1   = (const float*)d_in[10];
    const float* W2   = (const float*)d_in[11];
    const float* b2   = (const float*)d_in[12];
    const float* ln1g = (const float*)d_in[13];
    const float* ln1b = (const float*)d_in[14];
    const float* ln2g = (const float*)d_in[15];
    const float* ln2b = (const float*)d_in[16];
    float* out = (float*)d_out;

    float *q, *k, *v, *ctx, *sa, *x1, *hh, *y;
    cudaGetSymbolAddress((void**)&q,   g_q);
    cudaGetSymbolAddress((void**)&k,   g_k);
    cudaGetSymbolAddress((void**)&v,   g_v);
    cudaGetSymbolAddress((void**)&ctx, g_ctx);
    cudaGetSymbolAddress((void**)&sa,  g_sa);
    cudaGetSymbolAddress((void**)&x1,  g_x1);
    cudaGetSymbolAddress((void**)&hh,  g_h);
    cudaGetSymbolAddress((void**)&y,   g_y);

    dim3 blk(256);
    // QKV projections (tf32 mma.sync tensor cores)
    gemm_mma<0><<<dim3(DIM / 128,  MROWS / 128), blk>>>(x, Wq, bq, nullptr, q, MROWS, DIM, DIM);
    gemm_mma<0><<<dim3(DIM / 128,  MROWS / 128), blk>>>(x, Wk, bk, nullptr, k, MROWS, DIM, DIM);
    gemm_mma<0><<<dim3(DIM / 128,  MROWS / 128), blk>>>(x, Wv, bv, nullptr, v, MROWS, DIM, DIM);

    // banded attention (64-query tiles)
    attn_kernel<<<dim3(SEQ / 64, NH, BATCH), blk>>>(q, k, v, ctx);

    // out projection + residual(x)
    gemm_mma<1><<<dim3(DIM / 128,  MROWS / 128), blk>>>(ctx, Wo, bo, x, sa, MROWS, DIM, DIM);
    ln_kernel<<<MROWS, 256>>>(sa, ln1g, ln1b, x1);

    // FFN
    gemm_mma<2><<<dim3(DFF_N / 128, MROWS / 128), blk>>>(x1, W1, b1, nullptr, hh, MROWS, DFF_N, DIM);
    gemm_mma<1><<<dim3(DIM / 128,  MROWS / 128), blk>>>(hh, W2, b2, x1, y, MROWS, DIM, DFF_N);

    // LN2 -> output
    ln_kernel<<<MROWS, 256>>>(y, ln2g, ln2b, out);
}